// round 15
// baseline (speedup 1.0000x reference)
#include <cuda_runtime.h>

#define IN_F   4096
#define OUT_F  4096
#define BATCH  16384

#define ROWCG    (IN_F / 4)           // 1024 float4 per W row
#define WGRID    1024                 // A1 blocks, 4 consecutive rows each
#define ROWS_PB  4                    // rows per A1 block (64KB slab)

// Scratch (no device allocation) — overwritten every launch sequence.
__device__ float4 g_partial4[WGRID * ROWCG];    // 16 MB (L2-resident)
__device__ float  g_ws[IN_F];
__device__ float  g_bsum;

// ---------------------------------------------------------------------------
// A1 (slab layout): block b owns W rows [4b, 4b+4) — one CONTIGUOUS 64KB
// slab, read fully sequentially (rowdot-style locality). Thread t keeps 4
// float4 accumulators for col-groups t, t+256, t+512, t+768; per (row,q)
// the warp's 32 lanes read 512B coalesced. 16 loads/thread.
// Partial set per block: g_partial4[b*1024 + cg], coalesced stores.
// ---------------------------------------------------------------------------
__global__ __launch_bounds__(256)
void wsum_partial_kernel(const float4* __restrict__ W4) {
    const int t = threadIdx.x;
    const float4* slab = W4 + (size_t)blockIdx.x * ROWS_PB * ROWCG;

    float4 a0 = make_float4(0.f, 0.f, 0.f, 0.f);
    float4 a1 = a0, a2 = a0, a3 = a0;

    #pragma unroll 2
    for (int r = 0; r < ROWS_PB; ++r) {
        const float4* row = slab + (size_t)r * ROWCG;
        float4 v0 = row[t];
        float4 v1 = row[t + 256];
        float4 v2 = row[t + 512];
        float4 v3 = row[t + 768];
        a0.x += v0.x; a0.y += v0.y; a0.z += v0.z; a0.w += v0.w;
        a1.x += v1.x; a1.y += v1.y; a1.z += v1.z; a1.w += v1.w;
        a2.x += v2.x; a2.y += v2.y; a2.z += v2.z; a2.w += v2.w;
        a3.x += v3.x; a3.y += v3.y; a3.z += v3.z; a3.w += v3.w;
    }

    float4* dst = g_partial4 + (size_t)blockIdx.x * ROWCG;
    dst[t]       = a0;
    dst[t + 256] = a1;
    dst[t + 512] = a2;
    dst[t + 768] = a3;
}

// ---------------------------------------------------------------------------
// A2: finalize ws + bias. 128 blocks x 256, PDL-gated on A1.
// Block b owns col-groups [b*32, b*32+32). Warp w sums partial sets
// s in [w*128, w*128+128): lane l reads g_partial4[s*1024 + b*32 + l] —
// the warp's 32 lanes are CONTIGUOUS (512B coalesced) every iteration.
// Cross-warp reduce via smem in fixed order -> deterministic.
// Block 0 also reduces bias -> g_bsum.
// ---------------------------------------------------------------------------
__global__ __launch_bounds__(256)
void wsum_finalize_kernel(const float* __restrict__ bias) {
    cudaGridDependencySynchronize();   // wait for A1 (PDL)

    __shared__ float4 sh[8][32];
    const int t    = threadIdx.x;
    const int lane = t & 31;
    const int w    = t >> 5;                                  // 0..7
    const int cg   = (blockIdx.x << 5) + lane;                // col-group

    float4 a = make_float4(0.f, 0.f, 0.f, 0.f);
    #pragma unroll 8
    for (int s = w * 128; s < w * 128 + 128; ++s) {
        float4 v = g_partial4[(size_t)s * ROWCG + cg];
        a.x += v.x; a.y += v.y; a.z += v.z; a.w += v.w;
    }
    sh[w][lane] = a;
    __syncthreads();

    if (w == 0) {
        float4 r = sh[0][lane];
        #pragma unroll
        for (int m = 1; m < 8; ++m) {
            float4 v = sh[m][lane];
            r.x += v.x; r.y += v.y; r.z += v.z; r.w += v.w;
        }
        reinterpret_cast<float4*>(g_ws)[cg] = r;
    }

    if (blockIdx.x == 0) {
        __syncthreads();
        float b = 0.f;
        #pragma unroll
        for (int i = t; i < OUT_F; i += 256)
            b += __ldg(&bias[i]);
        #pragma unroll
        for (int o = 16; o > 0; o >>= 1)
            b += __shfl_xor_sync(0xffffffffu, b, o);
        __shared__ float shb[8];
        if (lane == 0) shb[w] = b;
        __syncthreads();
        if (t == 0) {
            float s = 0.f;
            #pragma unroll
            for (int m = 0; m < 8; ++m) s += shb[m];
            g_bsum = s;
        }
    }
}

// ---------------------------------------------------------------------------
// B: out[row] = dot(x[row], ws) + bsum. One warp per row — R3/R14-proven
// loop (44.6us @77% DRAM). PDL: prefetch 4 float4 of x per lane before the
// dependency sync so the x stream ramps during A2's tail. Fixed accumulation
// order -> deterministic.
// ---------------------------------------------------------------------------
__global__ __launch_bounds__(256)
void rowdot_kernel(const float4* __restrict__ x4,
                   float* __restrict__ out) {
    int gwarp = (blockIdx.x * blockDim.x + threadIdx.x) >> 5;  // 0..16383
    int lane  = threadIdx.x & 31;

    const float4* xr = x4 + (size_t)gwarp * ROWCG;
    float4 p0 = xr[lane];
    float4 p1 = xr[lane + 32];
    float4 p2 = xr[lane + 64];
    float4 p3 = xr[lane + 96];

    cudaGridDependencySynchronize();   // ws/bsum ready (PDL)

    const float4* ws4 = reinterpret_cast<const float4*>(g_ws);
    float4 w0 = __ldg(&ws4[lane]);
    float4 w1 = __ldg(&ws4[lane + 32]);
    float4 w2 = __ldg(&ws4[lane + 64]);
    float4 w3 = __ldg(&ws4[lane + 96]);

    float acc = p0.x * w0.x + p0.y * w0.y + p0.z * w0.z + p0.w * w0.w;
    acc      += p1.x * w1.x + p1.y * w1.y + p1.z * w1.z + p1.w * w1.w;
    acc      += p2.x * w2.x + p2.y * w2.y + p2.z * w2.z + p2.w * w2.w;
    acc      += p3.x * w3.x + p3.y * w3.y + p3.z * w3.z + p3.w * w3.w;

    #pragma unroll 8
    for (int i = lane + 128; i < ROWCG; i += 32) {
        float4 xv = xr[i];
        float4 wv = __ldg(&ws4[i]);
        acc += xv.x * wv.x + xv.y * wv.y + xv.z * wv.z + xv.w * wv.w;
    }
    #pragma unroll
    for (int o = 16; o > 0; o >>= 1)
        acc += __shfl_xor_sync(0xffffffffu, acc, o);
    if (lane == 0)
        out[gwarp] = acc + g_bsum;
}

extern "C" void kernel_launch(void* const* d_in, const int* in_sizes, int n_in,
                              void* d_out, int out_size) {
    const float* x    = (const float*)d_in[0];   // [BATCH, IN_F]
    const float* W    = (const float*)d_in[1];   // [OUT_F, IN_F]
    const float* bias = (const float*)d_in[2];   // [OUT_F]
    float* out = (float*)d_out;                  // [BATCH, 1]
    (void)in_sizes; (void)n_in; (void)out_size;

    // A1: plain launch (slab layout).
    wsum_partial_kernel<<<WGRID, 256>>>(reinterpret_cast<const float4*>(W));

    // A2 + rowdot with programmatic dependent launch: prologues overlap the
    // predecessor's tail; cudaGridDependencySynchronize enforces ordering.
    cudaLaunchAttribute attr[1];
    attr[0].id = cudaLaunchAttributeProgrammaticStreamSerialization;
    attr[0].val.programmaticStreamSerializationAllowed = 1;

    {
        cudaLaunchConfig_t cfg = {};
        cfg.gridDim  = dim3(IN_F / 32, 1, 1);    // 128 blocks
        cfg.blockDim = dim3(256, 1, 1);
        cfg.stream   = 0;
        cfg.attrs    = attr;
        cfg.numAttrs = 1;
        cudaLaunchKernelEx(&cfg, wsum_finalize_kernel, bias);
    }
    {
        cudaLaunchConfig_t cfg = {};
        cfg.gridDim  = dim3((BATCH * 32) / 256, 1, 1);  // 2048 blocks
        cfg.blockDim = dim3(256, 1, 1);
        cfg.stream   = 0;
        cfg.attrs    = attr;
        cfg.numAttrs = 1;
        cudaLaunchKernelEx(&cfg, rowdot_kernel,
                           reinterpret_cast<const float4*>(x), out);
    }
}

// round 16
// speedup vs baseline: 1.2090x; 1.2090x over previous
#include <cuda_runtime.h>

#define IN_F   4096
#define OUT_F  4096
#define BATCH  16384

#define NSPLIT   256                  // row splits for W partials
#define ROWS_PS  (OUT_F / NSPLIT)     // 16 rows per split
#define ROWCG    (IN_F / 4)           // 1024 float4 per W row

// Scratch (no device allocation) — overwritten every launch sequence.
__device__ float4 g_partial4[NSPLIT * ROWCG];   // 4 MB (L2-resident)
__device__ float  g_ws[IN_F];
__device__ float  g_bsum;

// ---------------------------------------------------------------------------
// A1: partial column sums of W — EXACT R8 structure (measured 13.5us @63.5%,
// best of 6 variants; slab/ldcs/unroll-16 all regressed).
// tid -> colg = tid&1023, split = tid>>10. Coalesced float4 reads of 16
// rows (stride 16KB), unroll 4. 1024 blocks x 256.
// ---------------------------------------------------------------------------
__global__ __launch_bounds__(256)
void wsum_partial_kernel(const float4* __restrict__ W4) {
    int tid   = blockIdx.x * blockDim.x + threadIdx.x;
    int colg  = tid & (ROWCG - 1);                    // 0..1023
    int split = tid >> 10;                            // 0..255

    const float4* p = W4 + (size_t)(split * ROWS_PS) * ROWCG + colg;
    float4 acc = make_float4(0.f, 0.f, 0.f, 0.f);
    #pragma unroll 4
    for (int r = 0; r < ROWS_PS; ++r) {
        float4 v = p[(size_t)r * ROWCG];
        acc.x += v.x; acc.y += v.y; acc.z += v.z; acc.w += v.w;
    }
    g_partial4[(split << 10) + colg] = acc;
}

// ---------------------------------------------------------------------------
// A2: finalize ws + bias — R14 structure (shuffle reduce), PDL-gated on A1.
// Block b owns colgroups [b*8, b*8+8); thread (c = t>>5, lane) sums splits
// {lane, lane+32, ..., lane+224}, then shuffle-xor reduce per component
// (fixed order -> deterministic). Block 0 also reduces bias -> g_bsum.
// ---------------------------------------------------------------------------
__global__ __launch_bounds__(256)
void wsum_finalize_kernel(const float* __restrict__ bias) {
    cudaGridDependencySynchronize();   // wait for A1 (PDL)

    const int t    = threadIdx.x;
    const int lane = t & 31;
    const int c    = t >> 5;                                  // 0..7
    const int cg   = (blockIdx.x << 3) + c;                   // colgroup 0..1023

    float4 a = make_float4(0.f, 0.f, 0.f, 0.f);
    #pragma unroll 8
    for (int k = 0; k < 8; ++k) {
        float4 v = g_partial4[((lane + (k << 5)) << 10) + cg];
        a.x += v.x; a.y += v.y; a.z += v.z; a.w += v.w;
    }
    #pragma unroll
    for (int o = 16; o > 0; o >>= 1) {
        a.x += __shfl_xor_sync(0xffffffffu, a.x, o);
        a.y += __shfl_xor_sync(0xffffffffu, a.y, o);
        a.z += __shfl_xor_sync(0xffffffffu, a.z, o);
        a.w += __shfl_xor_sync(0xffffffffu, a.w, o);
    }
    if (lane == 0)
        reinterpret_cast<float4*>(g_ws)[cg] = a;

    if (blockIdx.x == 0) {
        __syncthreads();
        float b = 0.f;
        #pragma unroll
        for (int i = t; i < OUT_F; i += 256)
            b += __ldg(&bias[i]);
        #pragma unroll
        for (int o = 16; o > 0; o >>= 1)
            b += __shfl_xor_sync(0xffffffffu, b, o);
        __shared__ float shb[8];
        if (lane == 0) shb[t >> 5] = b;
        __syncthreads();
        if (t == 0) {
            float s = 0.f;
            #pragma unroll
            for (int m = 0; m < 8; ++m) s += shb[m];
            g_bsum = s;
        }
    }
}

// ---------------------------------------------------------------------------
// B: TWO adjacent rows per warp. Per iteration: 2 independent x loads
// (doubled per-warp MLP vs the 1-row version's measured 77% DRAM) + 1 shared
// ws load (amortized over both rows). Prefetch 2 float4 per row before the
// PDL dependency sync so the x stream ramps under A2's tail. Fixed
// accumulation + shuffle order -> deterministic. 8192 warps (1024 blocks).
// ---------------------------------------------------------------------------
__global__ __launch_bounds__(256)
void rowdot_kernel(const float4* __restrict__ x4,
                   float* __restrict__ out) {
    int gwarp = (blockIdx.x * blockDim.x + threadIdx.x) >> 5;  // 0..8191
    int lane  = threadIdx.x & 31;
    int row   = gwarp << 1;

    const float4* xa = x4 + (size_t)row * ROWCG;
    const float4* xb = xa + ROWCG;

    float4 pa0 = xa[lane];
    float4 pa1 = xa[lane + 32];
    float4 pb0 = xb[lane];
    float4 pb1 = xb[lane + 32];

    cudaGridDependencySynchronize();   // ws/bsum ready (PDL)

    const float4* ws4 = reinterpret_cast<const float4*>(g_ws);
    float4 w0 = __ldg(&ws4[lane]);
    float4 w1 = __ldg(&ws4[lane + 32]);

    float accA = pa0.x * w0.x + pa0.y * w0.y + pa0.z * w0.z + pa0.w * w0.w
               + pa1.x * w1.x + pa1.y * w1.y + pa1.z * w1.z + pa1.w * w1.w;
    float accB = pb0.x * w0.x + pb0.y * w0.y + pb0.z * w0.z + pb0.w * w0.w
               + pb1.x * w1.x + pb1.y * w1.y + pb1.z * w1.z + pb1.w * w1.w;

    #pragma unroll 8
    for (int i = lane + 64; i < ROWCG; i += 32) {
        float4 wv = __ldg(&ws4[i]);
        float4 va = xa[i];
        float4 vb = xb[i];
        accA += va.x * wv.x + va.y * wv.y + va.z * wv.z + va.w * wv.w;
        accB += vb.x * wv.x + vb.y * wv.y + vb.z * wv.z + vb.w * wv.w;
    }
    #pragma unroll
    for (int o = 16; o > 0; o >>= 1) {
        accA += __shfl_xor_sync(0xffffffffu, accA, o);
        accB += __shfl_xor_sync(0xffffffffu, accB, o);
    }
    if (lane == 0) {
        float bs = g_bsum;
        out[row]     = accA + bs;
        out[row + 1] = accB + bs;
    }
}

extern "C" void kernel_launch(void* const* d_in, const int* in_sizes, int n_in,
                              void* d_out, int out_size) {
    const float* x    = (const float*)d_in[0];   // [BATCH, IN_F]
    const float* W    = (const float*)d_in[1];   // [OUT_F, IN_F]
    const float* bias = (const float*)d_in[2];   // [OUT_F]
    float* out = (float*)d_out;                  // [BATCH, 1]
    (void)in_sizes; (void)n_in; (void)out_size;

    // A1: plain launch (R8-proven mapping).
    wsum_partial_kernel<<<(NSPLIT * ROWCG) / 256, 256>>>(
        reinterpret_cast<const float4*>(W));

    // A2 + rowdot with programmatic dependent launch: prologues overlap the
    // predecessor's tail; cudaGridDependencySynchronize enforces ordering.
    cudaLaunchAttribute attr[1];
    attr[0].id = cudaLaunchAttributeProgrammaticStreamSerialization;
    attr[0].val.programmaticStreamSerializationAllowed = 1;

    {
        cudaLaunchConfig_t cfg = {};
        cfg.gridDim  = dim3(IN_F / 32, 1, 1);    // 128 blocks
        cfg.blockDim = dim3(256, 1, 1);
        cfg.stream   = 0;
        cfg.attrs    = attr;
        cfg.numAttrs = 1;
        cudaLaunchKernelEx(&cfg, wsum_finalize_kernel, bias);
    }
    {
        cudaLaunchConfig_t cfg = {};
        cfg.gridDim  = dim3((BATCH / 2 * 32) / 256, 1, 1);  // 1024 blocks
        cfg.blockDim = dim3(256, 1, 1);
        cfg.stream   = 0;
        cfg.attrs    = attr;
        cfg.numAttrs = 1;
        cudaLaunchKernelEx(&cfg, rowdot_kernel,
                           reinterpret_cast<const float4*>(x), out);
    }
}

// round 17
// speedup vs baseline: 1.3245x; 1.0955x over previous
#include <cuda_runtime.h>

#define IN_F   4096
#define OUT_F  4096
#define BATCH  16384

#define NSPLIT   512                  // row splits for W partials (2 waves)
#define ROWS_PS  (OUT_F / NSPLIT)     // 8 rows per split
#define ROWCG    (IN_F / 4)           // 1024 float4 per W row

// Scratch (no device allocation) — overwritten every launch sequence.
__device__ float4 g_partial4[NSPLIT * ROWCG];   // 8 MB (L2-resident)
__device__ float  g_ws[IN_F];
__device__ float  g_bsum;

// ---------------------------------------------------------------------------
// A1: partial column sums of W — R8 access shape (coalesced 512B/warp rows,
// unroll 4) but NSPLIT=512 -> 2048 blocks ≈ 1.7 co-resident waves, so wave-2
// loads overlap wave-1 drain (rowdot-style pipelining of ramp/tail).
// ---------------------------------------------------------------------------
__global__ __launch_bounds__(256)
void wsum_partial_kernel(const float4* __restrict__ W4) {
    int tid   = blockIdx.x * blockDim.x + threadIdx.x;
    int colg  = tid & (ROWCG - 1);                    // 0..1023
    int split = tid >> 10;                            // 0..511

    const float4* p = W4 + (size_t)(split * ROWS_PS) * ROWCG + colg;
    float4 acc = make_float4(0.f, 0.f, 0.f, 0.f);
    #pragma unroll 4
    for (int r = 0; r < ROWS_PS; ++r) {
        float4 v = p[(size_t)r * ROWCG];
        acc.x += v.x; acc.y += v.y; acc.z += v.z; acc.w += v.w;
    }
    g_partial4[(split << 10) + colg] = acc;
}

// ---------------------------------------------------------------------------
// A2: finalize ws + bias, PDL-gated on A1. 128 blocks x 256.
// Block b owns colgroups [b*8, b*8+8); thread (c = t>>5, lane) sums splits
// {lane + 32k, k=0..15} (16 float4 loads, L2-resident), then shuffle-xor
// reduce per component (fixed order -> deterministic). Block 0 also
// reduces bias -> g_bsum.
// ---------------------------------------------------------------------------
__global__ __launch_bounds__(256)
void wsum_finalize_kernel(const float* __restrict__ bias) {
    cudaGridDependencySynchronize();   // wait for A1 (PDL)

    const int t    = threadIdx.x;
    const int lane = t & 31;
    const int c    = t >> 5;                                  // 0..7
    const int cg   = (blockIdx.x << 3) + c;                   // colgroup 0..1023

    float4 a = make_float4(0.f, 0.f, 0.f, 0.f);
    #pragma unroll 16
    for (int k = 0; k < 16; ++k) {
        float4 v = g_partial4[((lane + (k << 5)) << 10) + cg];
        a.x += v.x; a.y += v.y; a.z += v.z; a.w += v.w;
    }
    #pragma unroll
    for (int o = 16; o > 0; o >>= 1) {
        a.x += __shfl_xor_sync(0xffffffffu, a.x, o);
        a.y += __shfl_xor_sync(0xffffffffu, a.y, o);
        a.z += __shfl_xor_sync(0xffffffffu, a.z, o);
        a.w += __shfl_xor_sync(0xffffffffu, a.w, o);
    }
    if (lane == 0)
        reinterpret_cast<float4*>(g_ws)[cg] = a;

    if (blockIdx.x == 0) {
        __syncthreads();
        float b = 0.f;
        #pragma unroll
        for (int i = t; i < OUT_F; i += 256)
            b += __ldg(&bias[i]);
        #pragma unroll
        for (int o = 16; o > 0; o >>= 1)
            b += __shfl_xor_sync(0xffffffffu, b, o);
        __shared__ float shb[8];
        if (lane == 0) shb[t >> 5] = b;
        __syncthreads();
        if (t == 0) {
            float s = 0.f;
            #pragma unroll
            for (int m = 0; m < 8; ++m) s += shb[m];
            g_bsum = s;
        }
    }
}

// ---------------------------------------------------------------------------
// B: out[row] = dot(x[row], ws) + bsum. ONE row per warp (R3/R14-proven;
// the 2-row variant regressed). Single change vs R14: unroll 16 — deeper
// load batching, tested in isolation. PDL prefetch of 4 float4 before the
// dependency sync. Fixed accumulation order -> deterministic.
// ---------------------------------------------------------------------------
__global__ __launch_bounds__(256)
void rowdot_kernel(const float4* __restrict__ x4,
                   float* __restrict__ out) {
    int gwarp = (blockIdx.x * blockDim.x + threadIdx.x) >> 5;  // 0..16383
    int lane  = threadIdx.x & 31;

    const float4* xr = x4 + (size_t)gwarp * ROWCG;
    float4 p0 = xr[lane];
    float4 p1 = xr[lane + 32];
    float4 p2 = xr[lane + 64];
    float4 p3 = xr[lane + 96];

    cudaGridDependencySynchronize();   // ws/bsum ready (PDL)

    const float4* ws4 = reinterpret_cast<const float4*>(g_ws);
    float4 w0 = __ldg(&ws4[lane]);
    float4 w1 = __ldg(&ws4[lane + 32]);
    float4 w2 = __ldg(&ws4[lane + 64]);
    float4 w3 = __ldg(&ws4[lane + 96]);

    float acc = p0.x * w0.x + p0.y * w0.y + p0.z * w0.z + p0.w * w0.w;
    acc      += p1.x * w1.x + p1.y * w1.y + p1.z * w1.z + p1.w * w1.w;
    acc      += p2.x * w2.x + p2.y * w2.y + p2.z * w2.z + p2.w * w2.w;
    acc      += p3.x * w3.x + p3.y * w3.y + p3.z * w3.z + p3.w * w3.w;

    #pragma unroll 16
    for (int i = lane + 128; i < ROWCG; i += 32) {
        float4 xv = xr[i];
        float4 wv = __ldg(&ws4[i]);
        acc += xv.x * wv.x + xv.y * wv.y + xv.z * wv.z + xv.w * wv.w;
    }
    #pragma unroll
    for (int o = 16; o > 0; o >>= 1)
        acc += __shfl_xor_sync(0xffffffffu, acc, o);
    if (lane == 0)
        out[gwarp] = acc + g_bsum;
}

extern "C" void kernel_launch(void* const* d_in, const int* in_sizes, int n_in,
                              void* d_out, int out_size) {
    const float* x    = (const float*)d_in[0];   // [BATCH, IN_F]
    const float* W    = (const float*)d_in[1];   // [OUT_F, IN_F]
    const float* bias = (const float*)d_in[2];   // [OUT_F]
    float* out = (float*)d_out;                  // [BATCH, 1]
    (void)in_sizes; (void)n_in; (void)out_size;

    // A1: plain launch, 2048 blocks (~1.7 waves).
    wsum_partial_kernel<<<(NSPLIT * ROWCG) / 256, 256>>>(
        reinterpret_cast<const float4*>(W));

    // A2 + rowdot with programmatic dependent launch: prologues overlap the
    // predecessor's tail; cudaGridDependencySynchronize enforces ordering.
    cudaLaunchAttribute attr[1];
    attr[0].id = cudaLaunchAttributeProgrammaticStreamSerialization;
    attr[0].val.programmaticStreamSerializationAllowed = 1;

    {
        cudaLaunchConfig_t cfg = {};
        cfg.gridDim  = dim3(IN_F / 32, 1, 1);    // 128 blocks
        cfg.blockDim = dim3(256, 1, 1);
        cfg.stream   = 0;
        cfg.attrs    = attr;
        cfg.numAttrs = 1;
        cudaLaunchKernelEx(&cfg, wsum_finalize_kernel, bias);
    }
    {
        cudaLaunchConfig_t cfg = {};
        cfg.gridDim  = dim3((BATCH * 32) / 256, 1, 1);  // 2048 blocks
        cfg.blockDim = dim3(256, 1, 1);
        cfg.stream   = 0;
        cfg.attrs    = attr;
        cfg.numAttrs = 1;
        cudaLaunchKernelEx(&cfg, rowdot_kernel,
                           reinterpret_cast<const float4*>(x), out);
    }
}